// round 11
// baseline (speedup 1.0000x reference)
#include <cuda_runtime.h>
#include <cuda_bf16.h>
#include <cstdint>

#define T_STEPS 16384
#define D_IN    512
#define H_DIM   1024
#define O_DIM   512

// Recurrence: 64 CTAs x 256 threads (8 warps), 2 rows per warp -> 16 rows/CTA.
// Grid organized as 8 clusters x 8 CTAs for hierarchical barrier.
#define NCTA     64
#define NTHREADS 256
#define CLU      8

__device__ float    g_hs[T_STEPS * H_DIM];   // full history (exchange + GEMM input)
__device__ unsigned g_count;                 // step arrival counter (self-resetting)
__device__ unsigned g_done;                  // exit counter (self-resetting)

__device__ __forceinline__ float fast_tanh(float x) {
    float e = __expf(2.0f * x);
    return 1.0f - __fdividef(2.0f, e + 1.0f);
}

__device__ __forceinline__ unsigned ld_acq(const unsigned* p) {
    unsigned v;
    asm volatile("ld.acquire.gpu.global.u32 %0, [%1];" : "=r"(v) : "l"(p) : "memory");
    return v;
}

__global__ __launch_bounds__(NTHREADS, 1) __cluster_dims__(CLU, 1, 1)
void rnn_kernel(const int* __restrict__ inputs,
                const float* __restrict__ h0,
                const float* __restrict__ U,
                const float* __restrict__ W,
                const float* __restrict__ bh,
                float* __restrict__ out_hT)
{
    extern __shared__ int sIn[];             // 16384 tokens: 64 KB dynamic
    __shared__ float hs_s[H_DIM];            // staged previous hidden state: 4 KB
    __shared__ unsigned s_flag_mem;          // step-release flag (DSMEM target)
    volatile unsigned* s_flag = &s_flag_mem;

    const int tid  = threadIdx.x;
    const int lane = tid & 31;
    const int warp = tid >> 5;
    const int rowbase = blockIdx.x * 16 + warp * 2;
    const int myrow = rowbase + lane;        // valid for lane < 2

    unsigned rank;
    asm("mov.u32 %0, %%cluster_ctarank;" : "=r"(rank));

    unsigned flagS;                          // shared-window addr of s_flag
    asm("{ .reg .u64 t; cvta.to.shared.u64 t, %1; cvt.u32.u64 %0, t; }"
        : "=r"(flagS) : "l"((unsigned*)&s_flag_mem));

    if (tid == 0) s_flag_mem = 0u;           // fresh every launch -> replay-safe

    // Stage token sequence
    for (int i = tid; i < T_STEPS; i += NTHREADS) sIn[i] = inputs[i];

    // Register-resident W: 2 rows per warp, 32 cols per lane (proven R2 layout).
    float w0[32], w1[32];
    {
        const float* W0 = W + (size_t)rowbase * H_DIM;
        const float* W1 = W + (size_t)(rowbase + 1) * H_DIM;
#pragma unroll
        for (int j = 0; j < 8; j++) {
            float4 a = *(const float4*)&W0[j * 128 + lane * 4];
            w0[j*4+0] = a.x; w0[j*4+1] = a.y; w0[j*4+2] = a.z; w0[j*4+3] = a.w;
            float4 b = *(const float4*)&W1[j * 128 + lane * 4];
            w1[j*4+0] = b.x; w1[j*4+1] = b.y; w1[j*4+2] = b.z; w1[j*4+3] = b.w;
        }
    }

    float bias = 0.0f, ux = 0.0f;
    __syncthreads();                         // sIn + s_flag init done (block scope)
    if (lane < 2) {
        bias = bh[myrow];
        ux = U[(size_t)myrow * D_IN + sIn[0]];
    }

    // All cluster CTAs' flags must be initialized before any peer store can land.
    asm volatile("barrier.cluster.arrive.aligned;" ::: "memory");
    asm volatile("barrier.cluster.wait.aligned;"   ::: "memory");

    for (int t = 0; t < T_STEPS; t++) {
        // ---- stage h_{t-1} into smem (fresh address each step: cache-safe) ----
        const float* hprev = (t == 0) ? h0 : (g_hs + (size_t)(t - 1) * H_DIM);
        float4 hv4 = *(const float4*)&hprev[tid * 4];
        *(float4*)&hs_s[tid * 4] = hv4;

        // Prefetch next ux while staging drains
        float ux_next = 0.0f;
        if (lane < 2 && t + 1 < T_STEPS)
            ux_next = U[(size_t)myrow * D_IN + sIn[t + 1]];

        __syncthreads();                     // hs_s fully staged

        // ---- dot: 2 rows, 2 scalar accumulator chains each (proven R2) ----
        float a00 = 0.f, a01 = 0.f, a10 = 0.f, a11 = 0.f;
#pragma unroll
        for (int j = 0; j < 8; j++) {
            float4 hv = *(const float4*)&hs_s[j * 128 + lane * 4];
            a00 += w0[j*4+0] * hv.x;  a01 += w0[j*4+1] * hv.y;
            a00 += w0[j*4+2] * hv.z;  a01 += w0[j*4+3] * hv.w;
            a10 += w1[j*4+0] * hv.x;  a11 += w1[j*4+1] * hv.y;
            a10 += w1[j*4+2] * hv.z;  a11 += w1[j*4+3] * hv.w;
        }
        float r0 = a00 + a01;
        float r1 = a10 + a11;
#pragma unroll
        for (int s = 16; s > 0; s >>= 1) {
            r0 += __shfl_xor_sync(0xffffffffu, r0, s);
            r1 += __shfl_xor_sync(0xffffffffu, r1, s);
        }

        if (lane < 2) {
            float pre = ((lane == 0) ? r0 : r1) + ux + bias;
            g_hs[(size_t)t * H_DIM + myrow] = fast_tanh(pre);
        }
        ux = ux_next;

        // ---- hierarchical grid barrier ----
        if (t < T_STEPS - 1) {
            __syncthreads();                 // all 16 rows' STGs hb the release-RED
            if (tid == 0) {
                asm volatile("red.release.gpu.global.add.u32 [%0], %1;"
                             :: "l"(&g_count), "r"(1u) : "memory");
            }
            const unsigned tp1 = (unsigned)(t + 1);
            if (rank == 0) {
                // Leader: sole poller of the global counter for this cluster.
                if (tid == 0) {
                    const unsigned target = tp1 * (unsigned)NCTA;
                    while (ld_acq(&g_count) < target) { }
                    __threadfence();         // order acquired state before flag stores
#pragma unroll
                    for (int r = 1; r < CLU; r++) {
                        unsigned rem;
                        asm("mapa.shared::cluster.u32 %0, %1, %2;"
                            : "=r"(rem) : "r"(flagS), "r"(r));
                        asm volatile("st.shared::cluster.u32 [%0], %1;"
                                     :: "r"(rem), "r"(tp1) : "memory");
                    }
                }
                __syncthreads();             // leader CTA threads gated on tid0
            } else {
                // Peers: spin on LOCAL smem flag (broadcast LDS, no L2 traffic).
                while (*s_flag < tp1) { }
                __threadfence();             // gpu-scope acquire-side fence
                __syncthreads();             // protects hs_s write-after-read
            }
        }
    }

    // ---- exit dance (proven): done counter + reset for graph replays ----
    __syncthreads();
    if (tid == 0) {
        asm volatile("red.release.gpu.global.add.u32 [%0], %1;"
                     :: "l"(&g_done), "r"(1u) : "memory");
    }
    if (blockIdx.x == 0) {
        if (tid == 0) {
            while (ld_acq(&g_done) < (unsigned)NCTA) { }
            g_count = 0u;                    // no CTA touches these anymore
            g_done  = 0u;
        }
        __syncthreads();
        __threadfence();
        for (int i = tid; i < H_DIM; i += NTHREADS)
            out_hT[i] = g_hs[(size_t)(T_STEPS - 1) * H_DIM + i];
    }

    // No CTA exits while a peer's DSMEM store could still be in flight.
    asm volatile("barrier.cluster.arrive.aligned;" ::: "memory");
    asm volatile("barrier.cluster.wait.aligned;"   ::: "memory");
}

// ---------------------------------------------------------------------------
// logits = hs @ V^T + by : C[16384 x 512] = A[16384 x 1024] * V[512 x 1024]^T
// 128x64x16 tiles, 256 threads, 8x4 register microtiles. (proven, 412us)
// ---------------------------------------------------------------------------
#define BM 128
#define BN 64
#define BK 16

__global__ __launch_bounds__(256)
void gemm_kernel(const float* __restrict__ A,
                 const float* __restrict__ V,
                 const float* __restrict__ by,
                 float* __restrict__ C)
{
    __shared__ float As[BK][BM + 4];
    __shared__ float Bs[BK][BN + 4];

    const int tid = threadIdx.x;
    const int bm  = blockIdx.y * BM;
    const int bn  = blockIdx.x * BN;
    const int tx  = tid & 15;
    const int ty  = tid >> 4;

    const int ar = tid >> 1;
    const int ak = (tid & 1) * 8;
    const int br = tid >> 2;
    const int bk = (tid & 3) * 4;

    float acc[8][4];
#pragma unroll
    for (int i = 0; i < 8; i++)
#pragma unroll
        for (int j = 0; j < 4; j++) acc[i][j] = 0.f;

    for (int kt = 0; kt < H_DIM; kt += BK) {
        float4 a0 = *(const float4*)&A[(size_t)(bm + ar) * H_DIM + kt + ak];
        float4 a1 = *(const float4*)&A[(size_t)(bm + ar) * H_DIM + kt + ak + 4];
        float4 bv = *(const float4*)&V[(size_t)(bn + br) * H_DIM + kt + bk];
        As[ak + 0][ar] = a0.x; As[ak + 1][ar] = a0.y;
        As[ak + 2][ar] = a0.z; As[ak + 3][ar] = a0.w;
        As[ak + 4][ar] = a1.x; As[ak + 5][ar] = a1.y;
        As[ak + 6][ar] = a1.z; As[ak + 7][ar] = a1.w;
        Bs[bk + 0][br] = bv.x; Bs[bk + 1][br] = bv.y;
        Bs[bk + 2][br] = bv.z; Bs[bk + 3][br] = bv.w;
        __syncthreads();

#pragma unroll
        for (int k = 0; k < BK; k++) {
            float4 rb  = *(const float4*)&Bs[k][tx * 4];
            float4 ra0 = *(const float4*)&As[k][ty * 8];
            float4 ra1 = *(const float4*)&As[k][ty * 8 + 4];
            float ra[8]  = {ra0.x, ra0.y, ra0.z, ra0.w, ra1.x, ra1.y, ra1.z, ra1.w};
            float rbb[4] = {rb.x, rb.y, rb.z, rb.w};
#pragma unroll
            for (int i = 0; i < 8; i++)
#pragma unroll
                for (int j = 0; j < 4; j++)
                    acc[i][j] += ra[i] * rbb[j];
        }
        __syncthreads();
    }

    const float4 byv = *(const float4*)&by[bn + tx * 4];
    const float bb[4] = {byv.x, byv.y, byv.z, byv.w};
#pragma unroll
    for (int i = 0; i < 8; i++) {
        float4 o;
        o.x = acc[i][0] + bb[0];
        o.y = acc[i][1] + bb[1];
        o.z = acc[i][2] + bb[2];
        o.w = acc[i][3] + bb[3];
        *(float4*)&C[(size_t)(bm + ty * 8 + i) * O_DIM + bn + tx * 4] = o;
    }
}

extern "C" void kernel_launch(void* const* d_in, const int* in_sizes, int n_in,
                              void* d_out, int out_size)
{
    (void)in_sizes; (void)n_in; (void)out_size;
    const int*   inputs = (const int*)  d_in[0];
    const float* h0     = (const float*)d_in[1];
    const float* U      = (const float*)d_in[2];
    const float* W      = (const float*)d_in[3];
    const float* V      = (const float*)d_in[4];
    const float* bh     = (const float*)d_in[5];
    const float* by     = (const float*)d_in[6];

    float* logits = (float*)d_out;
    float* out_hT = (float*)d_out + (size_t)T_STEPS * O_DIM;

    cudaFuncSetAttribute(rnn_kernel,
                         cudaFuncAttributeMaxDynamicSharedMemorySize,
                         T_STEPS * (int)sizeof(int));

    rnn_kernel<<<NCTA, NTHREADS, T_STEPS * sizeof(int)>>>(inputs, h0, U, W, bh, out_hT);

    static float* hs_ptr = nullptr;
    if (!hs_ptr) { void* p = nullptr; cudaGetSymbolAddress(&p, g_hs); hs_ptr = (float*)p; }

    dim3 ggrid(O_DIM / BN, T_STEPS / BM);
    gemm_kernel<<<ggrid, 256>>>(hs_ptr, V, by, logits);
}

// round 12
// speedup vs baseline: 1.1146x; 1.1146x over previous
#include <cuda_runtime.h>
#include <cuda_bf16.h>
#include <cstdint>

#define T_STEPS 16384
#define D_IN    512
#define H_DIM   1024
#define O_DIM   512

// Recurrence: 32 CTAs x 512 threads (16 warps), 2 rows per warp -> 32 rows/CTA.
// Same 16384 threads / same per-thread W share as the proven R2 kernel;
// ONLY the grid shape (barrier participant count) changes.
#define NCTA     32
#define NTHREADS 512

__device__ float    g_hs[T_STEPS * H_DIM];  // full history (exchange + GEMM input)
__device__ unsigned g_count;                 // step barrier counter (self-resetting)
__device__ unsigned g_done;                  // exit counter (self-resetting)

__device__ __forceinline__ float fast_tanh(float x) {
    float e = __expf(2.0f * x);
    return 1.0f - __fdividef(2.0f, e + 1.0f);
}

__global__ __launch_bounds__(NTHREADS, 1)
void rnn_kernel(const int* __restrict__ inputs,
                const float* __restrict__ h0,
                const float* __restrict__ U,
                const float* __restrict__ W,
                const float* __restrict__ bh,
                float* __restrict__ out_hT)
{
    extern __shared__ int sIn[];             // 16384 tokens: 64 KB dynamic
    __shared__ float hs_s[H_DIM];            // staged previous hidden state: 4 KB

    const int tid  = threadIdx.x;
    const int lane = tid & 31;
    const int warp = tid >> 5;
    const int rowbase = blockIdx.x * 32 + warp * 2;   // 32 rows per CTA
    const int myrow = rowbase + lane;        // valid for lane < 2

    // Stage token sequence
    for (int i = tid; i < T_STEPS; i += NTHREADS) sIn[i] = inputs[i];

    // Register-resident W: 2 rows per warp, 32 cols per lane (proven layout).
    float w0[32], w1[32];
    {
        const float* W0 = W + (size_t)rowbase * H_DIM;
        const float* W1 = W + (size_t)(rowbase + 1) * H_DIM;
#pragma unroll
        for (int j = 0; j < 8; j++) {
            float4 a = *(const float4*)&W0[j * 128 + lane * 4];
            w0[j*4+0] = a.x; w0[j*4+1] = a.y; w0[j*4+2] = a.z; w0[j*4+3] = a.w;
            float4 b = *(const float4*)&W1[j * 128 + lane * 4];
            w1[j*4+0] = b.x; w1[j*4+1] = b.y; w1[j*4+2] = b.z; w1[j*4+3] = b.w;
        }
    }

    float bias = 0.0f, ux = 0.0f;
    __syncthreads();                         // sIn ready
    if (lane < 2) {
        bias = bh[myrow];
        ux = U[(size_t)myrow * D_IN + sIn[0]];
    }

    volatile unsigned* cnt = &g_count;

    for (int t = 0; t < T_STEPS; t++) {
        // ---- stage h_{t-1} into smem (512 threads x float2 = 1024 floats) ----
        const float* hprev = (t == 0) ? h0 : (g_hs + (size_t)(t - 1) * H_DIM);
        float2 hv2 = *(const float2*)&hprev[tid * 2];
        *(float2*)&hs_s[tid * 2] = hv2;

        // Prefetch next ux while staging drains
        float ux_next = 0.0f;
        if (lane < 2 && t + 1 < T_STEPS)
            ux_next = U[(size_t)myrow * D_IN + sIn[t + 1]];

        __syncthreads();                     // hs_s fully staged

        // ---- dot: 2 rows, 2 accumulator chains each (proven R2 core) ----
        float a00 = 0.f, a01 = 0.f, a10 = 0.f, a11 = 0.f;
#pragma unroll
        for (int j = 0; j < 8; j++) {
            float4 hv = *(const float4*)&hs_s[j * 128 + lane * 4];
            a00 += w0[j*4+0] * hv.x;  a01 += w0[j*4+1] * hv.y;
            a00 += w0[j*4+2] * hv.z;  a01 += w0[j*4+3] * hv.w;
            a10 += w1[j*4+0] * hv.x;  a11 += w1[j*4+1] * hv.y;
            a10 += w1[j*4+2] * hv.z;  a11 += w1[j*4+3] * hv.w;
        }
        float r0 = a00 + a01;
        float r1 = a10 + a11;
#pragma unroll
        for (int s = 16; s > 0; s >>= 1) {
            r0 += __shfl_xor_sync(0xffffffffu, r0, s);
            r1 += __shfl_xor_sync(0xffffffffu, r1, s);
        }

        if (lane < 2) {
            float pre = ((lane == 0) ? r0 : r1) + ux + bias;
            g_hs[(size_t)t * H_DIM + myrow] = fast_tanh(pre);
        }
        ux = ux_next;

        // ---- grid barrier: VERBATIM R2 (the only variant measured fast) ----
        if (t < T_STEPS - 1) {
            __syncthreads();
            if (tid == 0) {
                __threadfence();                 // make this CTA's h writes visible
                atomicAdd(&g_count, 1u);         // RED.GLOBAL (no return use)
                const unsigned target = (unsigned)(t + 1) * NCTA;
                while (*cnt < target) { }        // L2-hit volatile poll
                __threadfence();                 // acquire
            }
            __syncthreads();
        }
    }

    // ---- exit dance: done counter + reset for graph replays (proven) ----
    __syncthreads();
    if (tid == 0) {
        __threadfence();
        atomicAdd(&g_done, 1u);
    }
    if (blockIdx.x == 0) {
        if (tid == 0) {
            volatile unsigned* dn = &g_done;
            while (*dn < (unsigned)NCTA) { }
            __threadfence();
            g_count = 0u;                        // no CTA touches these anymore
            g_done  = 0u;
        }
        __syncthreads();
        for (int i = tid; i < H_DIM; i += NTHREADS)
            out_hT[i] = g_hs[(size_t)(T_STEPS - 1) * H_DIM + i];
    }
}

// ---------------------------------------------------------------------------
// logits = hs @ V^T + by : C[16384 x 512] = A[16384 x 1024] * V[512 x 1024]^T
// 128x64x16 tiles, 256 threads, 8x4 register microtiles. (proven, 412us)
// ---------------------------------------------------------------------------
#define BM 128
#define BN 64
#define BK 16

__global__ __launch_bounds__(256)
void gemm_kernel(const float* __restrict__ A,
                 const float* __restrict__ V,
                 const float* __restrict__ by,
                 float* __restrict__ C)
{
    __shared__ float As[BK][BM + 4];
    __shared__ float Bs[BK][BN + 4];

    const int tid = threadIdx.x;
    const int bm  = blockIdx.y * BM;
    const int bn  = blockIdx.x * BN;
    const int tx  = tid & 15;
    const int ty  = tid >> 4;

    const int ar = tid >> 1;
    const int ak = (tid & 1) * 8;
    const int br = tid >> 2;
    const int bk = (tid & 3) * 4;

    float acc[8][4];
#pragma unroll
    for (int i = 0; i < 8; i++)
#pragma unroll
        for (int j = 0; j < 4; j++) acc[i][j] = 0.f;

    for (int kt = 0; kt < H_DIM; kt += BK) {
        float4 a0 = *(const float4*)&A[(size_t)(bm + ar) * H_DIM + kt + ak];
        float4 a1 = *(const float4*)&A[(size_t)(bm + ar) * H_DIM + kt + ak + 4];
        float4 bv = *(const float4*)&V[(size_t)(bn + br) * H_DIM + kt + bk];
        As[ak + 0][ar] = a0.x; As[ak + 1][ar] = a0.y;
        As[ak + 2][ar] = a0.z; As[ak + 3][ar] = a0.w;
        As[ak + 4][ar] = a1.x; As[ak + 5][ar] = a1.y;
        As[ak + 6][ar] = a1.z; As[ak + 7][ar] = a1.w;
        Bs[bk + 0][br] = bv.x; Bs[bk + 1][br] = bv.y;
        Bs[bk + 2][br] = bv.z; Bs[bk + 3][br] = bv.w;
        __syncthreads();

#pragma unroll
        for (int k = 0; k < BK; k++) {
            float4 rb  = *(const float4*)&Bs[k][tx * 4];
            float4 ra0 = *(const float4*)&As[k][ty * 8];
            float4 ra1 = *(const float4*)&As[k][ty * 8 + 4];
            float ra[8]  = {ra0.x, ra0.y, ra0.z, ra0.w, ra1.x, ra1.y, ra1.z, ra1.w};
            float rbb[4] = {rb.x, rb.y, rb.z, rb.w};
#pragma unroll
            for (int i = 0; i < 8; i++)
#pragma unroll
                for (int j = 0; j < 4; j++)
                    acc[i][j] += ra[i] * rbb[j];
        }
        __syncthreads();
    }

    const float4 byv = *(const float4*)&by[bn + tx * 4];
    const float bb[4] = {byv.x, byv.y, byv.z, byv.w};
#pragma unroll
    for (int i = 0; i < 8; i++) {
        float4 o;
        o.x = acc[i][0] + bb[0];
        o.y = acc[i][1] + bb[1];
        o.z = acc[i][2] + bb[2];
        o.w = acc[i][3] + bb[3];
        *(float4*)&C[(size_t)(bm + ty * 8 + i) * O_DIM + bn + tx * 4] = o;
    }
}

extern "C" void kernel_launch(void* const* d_in, const int* in_sizes, int n_in,
                              void* d_out, int out_size)
{
    (void)in_sizes; (void)n_in; (void)out_size;
    const int*   inputs = (const int*)  d_in[0];
    const float* h0     = (const float*)d_in[1];
    const float* U      = (const float*)d_in[2];
    const float* W      = (const float*)d_in[3];
    const float* V      = (const float*)d_in[4];
    const float* bh     = (const float*)d_in[5];
    const float* by     = (const float*)d_in[6];

    float* logits = (float*)d_out;
    float* out_hT = (float*)d_out + (size_t)T_STEPS * O_DIM;

    cudaFuncSetAttribute(rnn_kernel,
                         cudaFuncAttributeMaxDynamicSharedMemorySize,
                         T_STEPS * (int)sizeof(int));

    rnn_kernel<<<NCTA, NTHREADS, T_STEPS * sizeof(int)>>>(inputs, h0, U, W, bh, out_hT);

    static float* hs_ptr = nullptr;
    if (!hs_ptr) { void* p = nullptr; cudaGetSymbolAddress(&p, g_hs); hs_ptr = (float*)p; }

    dim3 ggrid(O_DIM / BN, T_STEPS / BM);
    gemm_kernel<<<ggrid, 256>>>(hs_ptr, V, by, logits);
}

// round 14
// speedup vs baseline: 1.2310x; 1.1044x over previous
#include <cuda_runtime.h>
#include <cuda_bf16.h>
#include <cstdint>

#define T_STEPS 16384
#define D_IN    512
#define H_DIM   1024
#define O_DIM   512

// Recurrence: 64 CTAs x 256 threads (8 warps), 2 rows per warp -> 16 rows/CTA.
// This is the measured-champion R2 kernel with ONE change: the release-side
// __threadfence()+atomicAdd is fused into a single red.release.gpu.add.
#define NCTA     64
#define NTHREADS 256

__device__ float    g_hs[T_STEPS * H_DIM];  // full history (exchange + GEMM input)
__device__ unsigned g_count;                 // step barrier counter (self-resetting)
__device__ unsigned g_done;                  // exit counter (self-resetting)

__device__ __forceinline__ float fast_tanh(float x) {
    float e = __expf(2.0f * x);
    return 1.0f - __fdividef(2.0f, e + 1.0f);
}

__global__ __launch_bounds__(NTHREADS, 1)
void rnn_kernel(const int* __restrict__ inputs,
                const float* __restrict__ h0,
                const float* __restrict__ U,
                const float* __restrict__ W,
                const float* __restrict__ bh,
                float* __restrict__ out_hT)
{
    extern __shared__ int sIn[];             // 16384 tokens: 64 KB dynamic
    __shared__ float hs_s[H_DIM];            // staged previous hidden state: 4 KB

    const int tid  = threadIdx.x;
    const int lane = tid & 31;
    const int warp = tid >> 5;
    const int rowbase = blockIdx.x * 16 + warp * 2;
    const int myrow = rowbase + lane;        // valid for lane < 2

    // Stage token sequence
    for (int i = tid; i < T_STEPS; i += NTHREADS) sIn[i] = inputs[i];

    // Register-resident W: 2 rows per warp, 32 cols per lane (proven layout).
    float w0[32], w1[32];
    {
        const float* W0 = W + (size_t)rowbase * H_DIM;
        const float* W1 = W + (size_t)(rowbase + 1) * H_DIM;
#pragma unroll
        for (int j = 0; j < 8; j++) {
            float4 a = *(const float4*)&W0[j * 128 + lane * 4];
            w0[j*4+0] = a.x; w0[j*4+1] = a.y; w0[j*4+2] = a.z; w0[j*4+3] = a.w;
            float4 b = *(const float4*)&W1[j * 128 + lane * 4];
            w1[j*4+0] = b.x; w1[j*4+1] = b.y; w1[j*4+2] = b.z; w1[j*4+3] = b.w;
        }
    }

    float bias = 0.0f, ux = 0.0f;
    __syncthreads();                         // sIn ready
    if (lane < 2) {
        bias = bh[myrow];
        ux = U[(size_t)myrow * D_IN + sIn[0]];
    }

    volatile unsigned* cnt = &g_count;

    for (int t = 0; t < T_STEPS; t++) {
        // ---- stage h_{t-1} into smem (256 threads x float4 = 1024 floats) ----
        const float* hprev = (t == 0) ? h0 : (g_hs + (size_t)(t - 1) * H_DIM);
        float4 hv4 = *(const float4*)&hprev[tid * 4];
        *(float4*)&hs_s[tid * 4] = hv4;

        // Prefetch next ux while staging drains
        float ux_next = 0.0f;
        if (lane < 2 && t + 1 < T_STEPS)
            ux_next = U[(size_t)myrow * D_IN + sIn[t + 1]];

        __syncthreads();                     // hs_s fully staged

        // ---- dot: 2 rows, 2 accumulator chains each (proven R2 core) ----
        float a00 = 0.f, a01 = 0.f, a10 = 0.f, a11 = 0.f;
#pragma unroll
        for (int j = 0; j < 8; j++) {
            float4 hv = *(const float4*)&hs_s[j * 128 + lane * 4];
            a00 += w0[j*4+0] * hv.x;  a01 += w0[j*4+1] * hv.y;
            a00 += w0[j*4+2] * hv.z;  a01 += w0[j*4+3] * hv.w;
            a10 += w1[j*4+0] * hv.x;  a11 += w1[j*4+1] * hv.y;
            a10 += w1[j*4+2] * hv.z;  a11 += w1[j*4+3] * hv.w;
        }
        float r0 = a00 + a01;
        float r1 = a10 + a11;
#pragma unroll
        for (int s = 16; s > 0; s >>= 1) {
            r0 += __shfl_xor_sync(0xffffffffu, r0, s);
            r1 += __shfl_xor_sync(0xffffffffu, r1, s);
        }

        if (lane < 2) {
            float pre = ((lane == 0) ? r0 : r1) + ux + bias;
            g_hs[(size_t)t * H_DIM + myrow] = fast_tanh(pre);
        }
        ux = ux_next;

        // ---- grid barrier: R2 with release-RED (single change this round) ----
        if (t < T_STEPS - 1) {
            __syncthreads();                 // all 16 rows' STGs precede the RED
            if (tid == 0) {
                // release semantics make this CTA's h stores visible with the
                // counter increment: replaces __threadfence()+atomicAdd.
                asm volatile("red.release.gpu.global.add.u32 [%0], %1;"
                             :: "l"(&g_count), "r"(1u) : "memory");
                const unsigned target = (unsigned)(t + 1) * NCTA;
                while (*cnt < target) { }    // simple volatile poll (fastest measured)
                __threadfence();             // acquire: order counter before h loads
            }
            __syncthreads();                 // release workers
        }
    }

    // ---- exit dance: proven verbatim (done counter + reset for replays) ----
    __syncthreads();
    if (tid == 0) {
        __threadfence();
        atomicAdd(&g_done, 1u);
    }
    if (blockIdx.x == 0) {
        if (tid == 0) {
            volatile unsigned* dn = &g_done;
            while (*dn < (unsigned)NCTA) { }
            __threadfence();
            g_count = 0u;                    // no CTA touches these anymore
            g_done  = 0u;
        }
        __syncthreads();
        for (int i = tid; i < H_DIM; i += NTHREADS)
            out_hT[i] = g_hs[(size_t)(T_STEPS - 1) * H_DIM + i];
    }
}

// ---------------------------------------------------------------------------
// logits = hs @ V^T + by : C[16384 x 512] = A[16384 x 1024] * V[512 x 1024]^T
// 128x64x16 tiles, 256 threads, 8x4 register microtiles. (proven, 412us)
// ---------------------------------------------------------------------------
#define BM 128
#define BN 64
#define BK 16

__global__ __launch_bounds__(256)
void gemm_kernel(const float* __restrict__ A,
                 const float* __restrict__ V,
                 const float* __restrict__ by,
                 float* __restrict__ C)
{
    __shared__ float As[BK][BM + 4];
    __shared__ float Bs[BK][BN + 4];

    const int tid = threadIdx.x;
    const int bm  = blockIdx.y * BM;
    const int bn  = blockIdx.x * BN;
    const int tx  = tid & 15;
    const int ty  = tid >> 4;

    const int ar = tid >> 1;
    const int ak = (tid & 1) * 8;
    const int br = tid >> 2;
    const int bk = (tid & 3) * 4;

    float acc[8][4];
#pragma unroll
    for (int i = 0; i < 8; i++)
#pragma unroll
        for (int j = 0; j < 4; j++) acc[i][j] = 0.f;

    for (int kt = 0; kt < H_DIM; kt += BK) {
        float4 a0 = *(const float4*)&A[(size_t)(bm + ar) * H_DIM + kt + ak];
        float4 a1 = *(const float4*)&A[(size_t)(bm + ar) * H_DIM + kt + ak + 4];
        float4 bv = *(const float4*)&V[(size_t)(bn + br) * H_DIM + kt + bk];
        As[ak + 0][ar] = a0.x; As[ak + 1][ar] = a0.y;
        As[ak + 2][ar] = a0.z; As[ak + 3][ar] = a0.w;
        As[ak + 4][ar] = a1.x; As[ak + 5][ar] = a1.y;
        As[ak + 6][ar] = a1.z; As[ak + 7][ar] = a1.w;
        Bs[bk + 0][br] = bv.x; Bs[bk + 1][br] = bv.y;
        Bs[bk + 2][br] = bv.z; Bs[bk + 3][br] = bv.w;
        __syncthreads();

#pragma unroll
        for (int k = 0; k < BK; k++) {
            float4 rb  = *(const float4*)&Bs[k][tx * 4];
            float4 ra0 = *(const float4*)&As[k][ty * 8];
            float4 ra1 = *(const float4*)&As[k][ty * 8 + 4];
            float ra[8]  = {ra0.x, ra0.y, ra0.z, ra0.w, ra1.x, ra1.y, ra1.z, ra1.w};
            float rbb[4] = {rb.x, rb.y, rb.z, rb.w};
#pragma unroll
            for (int i = 0; i < 8; i++)
#pragma unroll
                for (int j = 0; j < 4; j++)
                    acc[i][j] += ra[i] * rbb[j];
        }
        __syncthreads();
    }

    const float4 byv = *(const float4*)&by[bn + tx * 4];
    const float bb[4] = {byv.x, byv.y, byv.z, byv.w};
#pragma unroll
    for (int i = 0; i < 8; i++) {
        float4 o;
        o.x = acc[i][0] + bb[0];
        o.y = acc[i][1] + bb[1];
        o.z = acc[i][2] + bb[2];
        o.w = acc[i][3] + bb[3];
        *(float4*)&C[(size_t)(bm + ty * 8 + i) * O_DIM + bn + tx * 4] = o;
    }
}

extern "C" void kernel_launch(void* const* d_in, const int* in_sizes, int n_in,
                              void* d_out, int out_size)
{
    (void)in_sizes; (void)n_in; (void)out_size;
    const int*   inputs = (const int*)  d_in[0];
    const float* h0     = (const float*)d_in[1];
    const float* U      = (const float*)d_in[2];
    const float* W      = (const float*)d_in[3];
    const float* V      = (const float*)d_in[4];
    const float* bh     = (const float*)d_in[5];
    const float* by     = (const float*)d_in[6];

    float* logits = (float*)d_out;
    float* out_hT = (float*)d_out + (size_t)T_STEPS * O_DIM;

    cudaFuncSetAttribute(rnn_kernel,
                         cudaFuncAttributeMaxDynamicSharedMemorySize,
                         T_STEPS * (int)sizeof(int));

    rnn_kernel<<<NCTA, NTHREADS, T_STEPS * sizeof(int)>>>(inputs, h0, U, W, bh, out_hT);

    static float* hs_ptr = nullptr;
    if (!hs_ptr) { void* p = nullptr; cudaGetSymbolAddress(&p, g_hs); hs_ptr = (float*)p; }

    dim3 ggrid(O_DIM / BN, T_STEPS / BM);
    gemm_kernel<<<ggrid, 256>>>(hs_ptr, V, by, logits);
}

// round 15
// speedup vs baseline: 1.4240x; 1.1568x over previous
#include <cuda_runtime.h>
#include <cuda_bf16.h>
#include <cstdint>

#define T_STEPS 16384
#define D_IN    512
#define H_DIM   1024
#define O_DIM   512

// Recurrence: 64 CTAs x 256 threads (8 warps), 2 rows per warp -> 16 rows/CTA.
// BYTE-IDENTICAL to the round-2 champion (28.7 ms) — reproducibility probe.
#define NCTA     64
#define NTHREADS 256
#define WARPS    8

__device__ float    g_hs[T_STEPS * H_DIM];  // full hidden-state history
__device__ unsigned g_count;                 // step barrier counter (self-resetting)
__device__ unsigned g_done;                  // exit barrier counter

__device__ __forceinline__ float fast_tanh(float x) {
    float e = __expf(2.0f * x);              // inf for large x, 0 for very negative -> correct limits
    return 1.0f - __fdividef(2.0f, e + 1.0f);
}

__global__ __launch_bounds__(NTHREADS, 1)
void rnn_kernel(const int* __restrict__ inputs,
                const float* __restrict__ h0,
                const float* __restrict__ U,
                const float* __restrict__ W,
                const float* __restrict__ bh,
                float* __restrict__ out_hT)
{
    extern __shared__ int sIn[];             // all T inputs: 64 KB
    __shared__ float hs_s[H_DIM];            // staged previous hidden state: 4 KB

    const int tid  = threadIdx.x;
    const int lane = tid & 31;
    const int warp = tid >> 5;
    const int rowbase = blockIdx.x * 16 + warp * 2;   // this warp's 2 rows

    // Stage token sequence
    for (int i = tid; i < T_STEPS; i += NTHREADS) sIn[i] = inputs[i];

    // Register-resident W slices for 2 rows (float4 coalesced loads)
    float w0[32], w1[32];
    {
        const float* W0 = W + (size_t)rowbase * H_DIM;
        const float* W1 = W + (size_t)(rowbase + 1) * H_DIM;
#pragma unroll
        for (int j = 0; j < 8; j++) {
            float4 a = *(const float4*)&W0[j * 128 + lane * 4];
            w0[j*4+0] = a.x; w0[j*4+1] = a.y; w0[j*4+2] = a.z; w0[j*4+3] = a.w;
            float4 b = *(const float4*)&W1[j * 128 + lane * 4];
            w1[j*4+0] = b.x; w1[j*4+1] = b.y; w1[j*4+2] = b.z; w1[j*4+3] = b.w;
        }
    }

    // Per-lane row constants (lanes 0 and 1 own rows rowbase+0 / rowbase+1)
    const int myrow = rowbase + lane;        // valid for lane < 2
    float bias = 0.0f, ux = 0.0f;
    __syncthreads();                         // sIn ready
    if (lane < 2) {
        bias = bh[myrow];
        ux = U[(size_t)myrow * D_IN + sIn[0]];
    }

    for (int t = 0; t < T_STEPS; t++) {
        // Stage h_{t-1} into smem (256 threads x float4 = 1024 floats)
        const float* hprev = (t == 0) ? h0 : (g_hs + (size_t)(t - 1) * H_DIM);
        float4 hv4 = *(const float4*)&hprev[tid * 4];
        *(float4*)&hs_s[tid * 4] = hv4;

        // Prefetch next ux (L2 hit on U) while staging completes
        float ux_next = 0.0f;
        if (lane < 2 && t + 1 < T_STEPS)
            ux_next = U[(size_t)myrow * D_IN + sIn[t + 1]];

        __syncthreads();                     // hs_s ready

        // Dot products: 2 rows, 2 accumulator chains each
        float a00 = 0.f, a01 = 0.f, a10 = 0.f, a11 = 0.f;
#pragma unroll
        for (int j = 0; j < 8; j++) {
            float4 hv = *(const float4*)&hs_s[j * 128 + lane * 4];
            a00 += w0[j*4+0] * hv.x;  a01 += w0[j*4+1] * hv.y;
            a00 += w0[j*4+2] * hv.z;  a01 += w0[j*4+3] * hv.w;
            a10 += w1[j*4+0] * hv.x;  a11 += w1[j*4+1] * hv.y;
            a10 += w1[j*4+2] * hv.z;  a11 += w1[j*4+3] * hv.w;
        }
        float r0 = a00 + a01;
        float r1 = a10 + a11;

        // Two interleaved butterfly reductions (latencies overlap)
#pragma unroll
        for (int s = 16; s > 0; s >>= 1) {
            r0 += __shfl_xor_sync(0xffffffffu, r0, s);
            r1 += __shfl_xor_sync(0xffffffffu, r1, s);
        }

        if (lane < 2) {
            float pre = ((lane == 0) ? r0 : r1) + ux + bias;
            g_hs[(size_t)t * H_DIM + myrow] = fast_tanh(pre);
        }
        ux = ux_next;

        if (t < T_STEPS - 1) {
            __syncthreads();                 // all rows written; also protects hs_s reuse
            if (tid == 0) {
                asm volatile("red.release.gpu.global.add.u32 [%0], %1;"
                             :: "l"(&g_count), "r"(1u) : "memory");
                const unsigned target = (unsigned)(t + 1) * NCTA;
                unsigned v;
                do {
                    asm volatile("ld.acquire.gpu.global.u32 %0, [%1];"
                                 : "=r"(v) : "l"(&g_count) : "memory");
                } while (v < target);
            }
            __syncthreads();                 // release workers
        }
    }

    // Exit: separate done-counter so g_count can be safely reset for the next replay
    __syncthreads();
    if (tid == 0) {
        asm volatile("red.release.gpu.global.add.u32 [%0], %1;"
                     :: "l"(&g_done), "r"(1u) : "memory");
    }
    if (blockIdx.x == 0) {
        if (tid == 0) {
            unsigned v;
            do {
                asm volatile("ld.acquire.gpu.global.u32 %0, [%1];"
                             : "=r"(v) : "l"(&g_done) : "memory");
            } while (v < NCTA);
            g_count = 0u;                    // no CTA reads these anymore
            g_done  = 0u;
        }
        __syncthreads();
        for (int i = tid; i < H_DIM; i += NTHREADS)
            out_hT[i] = g_hs[(size_t)(T_STEPS - 1) * H_DIM + i];
    }
}

// ---------------------------------------------------------------------------
// logits = hs @ V^T + by : C[16384 x 512] = A[16384 x 1024] * V[512 x 1024]^T
// NEW: 128x128x8 tiles, 256 threads, 8x8 register microtiles (2x arithmetic
// intensity vs the 412us 128x64 version, which ncu showed LDS-capped: L1 78%).
// ---------------------------------------------------------------------------
#define BM 128
#define BN 128
#define BK 8

__global__ __launch_bounds__(256)
void gemm_kernel(const float* __restrict__ A,
                 const float* __restrict__ V,
                 const float* __restrict__ by,
                 float* __restrict__ C)
{
    __shared__ float As[BK][BM + 4];   // [k][m]
    __shared__ float Bs[BK][BN + 4];   // [k][n]

    const int tid = threadIdx.x;
    const int bm  = blockIdx.y * BM;
    const int bn  = blockIdx.x * BN;
    const int tx  = tid & 15;          // 0..15 -> 8 output cols
    const int ty  = tid >> 4;          // 0..15 -> 8 output rows

    const int lr = tid >> 1;           // 0..127 tile row for loads
    const int lk = (tid & 1) * 4;      // 0 or 4: k-offset for loads

    float acc[8][8];
#pragma unroll
    for (int i = 0; i < 8; i++)
#pragma unroll
        for (int j = 0; j < 8; j++) acc[i][j] = 0.f;

    for (int kt = 0; kt < H_DIM; kt += BK) {
        // A tile (transposed into smem): As[k][m]
        float4 av = *(const float4*)&A[(size_t)(bm + lr) * H_DIM + kt + lk];
        As[lk + 0][lr] = av.x; As[lk + 1][lr] = av.y;
        As[lk + 2][lr] = av.z; As[lk + 3][lr] = av.w;
        // B tile: Bs[k][n] = V[n][k]
        float4 bv = *(const float4*)&V[(size_t)(bn + lr) * H_DIM + kt + lk];
        Bs[lk + 0][lr] = bv.x; Bs[lk + 1][lr] = bv.y;
        Bs[lk + 2][lr] = bv.z; Bs[lk + 3][lr] = bv.w;
        __syncthreads();

#pragma unroll
        for (int k = 0; k < BK; k++) {
            float4 ra0 = *(const float4*)&As[k][ty * 8];
            float4 ra1 = *(const float4*)&As[k][ty * 8 + 4];
            float4 rb0 = *(const float4*)&Bs[k][tx * 8];
            float4 rb1 = *(const float4*)&Bs[k][tx * 8 + 4];
            float ra[8] = {ra0.x, ra0.y, ra0.z, ra0.w, ra1.x, ra1.y, ra1.z, ra1.w};
            float rb[8] = {rb0.x, rb0.y, rb0.z, rb0.w, rb1.x, rb1.y, rb1.z, rb1.w};
#pragma unroll
            for (int i = 0; i < 8; i++)
#pragma unroll
                for (int j = 0; j < 8; j++)
                    acc[i][j] += ra[i] * rb[j];
        }
        __syncthreads();
    }

    const float4 byv0 = *(const float4*)&by[bn + tx * 8];
    const float4 byv1 = *(const float4*)&by[bn + tx * 8 + 4];
    const float bb[8] = {byv0.x, byv0.y, byv0.z, byv0.w,
                         byv1.x, byv1.y, byv1.z, byv1.w};
#pragma unroll
    for (int i = 0; i < 8; i++) {
        float4 o0, o1;
        o0.x = acc[i][0] + bb[0]; o0.y = acc[i][1] + bb[1];
        o0.z = acc[i][2] + bb[2]; o0.w = acc[i][3] + bb[3];
        o1.x = acc[i][4] + bb[4]; o1.y = acc[i][5] + bb[5];
        o1.z = acc[i][6] + bb[6]; o1.w = acc[i][7] + bb[7];
        *(float4*)&C[(size_t)(bm + ty * 8 + i) * O_DIM + bn + tx * 8]     = o0;
        *(float4*)&C[(size_t)(bm + ty * 8 + i) * O_DIM + bn + tx * 8 + 4] = o1;
    }
}

extern "C" void kernel_launch(void* const* d_in, const int* in_sizes, int n_in,
                              void* d_out, int out_size)
{
    (void)in_sizes; (void)n_in; (void)out_size;
    const int*   inputs = (const int*)  d_in[0];
    const float* h0     = (const float*)d_in[1];
    const float* U      = (const float*)d_in[2];
    const float* W      = (const float*)d_in[3];
    const float* V      = (const float*)d_in[4];
    const float* bh     = (const float*)d_in[5];
    const float* by     = (const float*)d_in[6];

    float* logits = (float*)d_out;                           // T*O
    float* out_hT = (float*)d_out + (size_t)T_STEPS * O_DIM; // + H

    cudaFuncSetAttribute(rnn_kernel,
                         cudaFuncAttributeMaxDynamicSharedMemorySize,
                         T_STEPS * (int)sizeof(int));

    rnn_kernel<<<NCTA, NTHREADS, T_STEPS * sizeof(int)>>>(inputs, h0, U, W, bh, out_hT);

    static float* hs_ptr = nullptr;
    if (!hs_ptr) { void* p = nullptr; cudaGetSymbolAddress(&p, g_hs); hs_ptr = (float*)p; }

    dim3 ggrid(O_DIM / BN, T_STEPS / BM);
    gemm_kernel<<<ggrid, 256>>>(hs_ptr, V, by, logits);
}